// round 13
// baseline (speedup 1.0000x reference)
#include <cuda_runtime.h>
#include <cuda_bf16.h>
#include <math.h>
#include <stdint.h>

#define BB   8
#define LL   2048
#define HH   1024
#define TT   256
#define M1   (BB * LL)    // 16384
#define M2   (BB * TT)    // 2048

// ---------------- scratch (__device__ globals; no allocation allowed) -------
__device__ float g_seq[(size_t)M1 * HH];                                // 64 MiB
__device__ float g_cell2[(size_t)M2 * HH];                              //  8 MiB
__device__ __align__(16) __nv_bfloat16 g_Ahi[(size_t)M1 * 2 * HH];      // 64 MiB
__device__ __align__(16) __nv_bfloat16 g_Alo[(size_t)M1 * 2 * HH];      // 64 MiB
__device__ __align__(16) __nv_bfloat16 g_c1hi[(size_t)M2 * HH];         //  4 MiB
__device__ __align__(16) __nv_bfloat16 g_c1lo[(size_t)M2 * HH];         //  4 MiB
__device__ __align__(16) __nv_bfloat16 g_WdT_hi[(size_t)HH * 2 * HH];   //  4 MiB
__device__ __align__(16) __nv_bfloat16 g_WdT_lo[(size_t)HH * 2 * HH];
__device__ __align__(16) __nv_bfloat16 g_WrT_hi[(size_t)HH * HH];       //  2 MiB
__device__ __align__(16) __nv_bfloat16 g_WrT_lo[(size_t)HH * HH];
__device__ int g_entries[BB * LL];
__device__ int g_offsets[BB * (TT + 1)];

// ---------------- helpers ----------------------------------------------------
__device__ __forceinline__ uint32_t smem_u32(const void* p) {
    uint32_t a;
    asm("{ .reg .u64 t; cvta.to.shared.u64 t, %1; cvt.u32.u64 %0, t; }" : "=r"(a) : "l"(p));
    return a;
}
__device__ __forceinline__ uint32_t pk_bf(__nv_bfloat16 a, __nv_bfloat16 b) {
    return (uint32_t)__bfloat16_as_ushort(a) | ((uint32_t)__bfloat16_as_ushort(b) << 16);
}
__device__ __forceinline__ float gelu_exact(float x) {
    return 0.5f * x * (1.0f + erff(x * 0.7071067811865475244f));
}
__device__ __forceinline__ void cp_async16(uint32_t dst, const void* src) {
    asm volatile("cp.async.cg.shared.global [%0], [%1], 16;" :: "r"(dst), "l"(src) : "memory");
}
__device__ __forceinline__ void cp_commit() { asm volatile("cp.async.commit_group;" ::: "memory"); }
__device__ __forceinline__ void cp_wait1()  { asm volatile("cp.async.wait_group 1;" ::: "memory"); }
__device__ __forceinline__ void cp_wait0()  { asm volatile("cp.async.wait_group 0;" ::: "memory"); }
__device__ __forceinline__ void mma_bf16_16816(float* c, const uint32_t* a,
                                               uint32_t b0, uint32_t b1) {
    asm volatile(
        "mma.sync.aligned.m16n8k16.row.col.f32.bf16.bf16.f32 "
        "{%0,%1,%2,%3}, {%4,%5,%6,%7}, {%8,%9}, {%0,%1,%2,%3};"
        : "+f"(c[0]), "+f"(c[1]), "+f"(c[2]), "+f"(c[3])
        : "r"(a[0]), "r"(a[1]), "r"(a[2]), "r"(a[3]), "r"(b0), "r"(b1));
}

// ---------------------------------------------------------------------------
// A pre-convert: g_Ahi/g_Alo[m][k] = bf16 hi/lo split of concat(former,hidden)
// ---------------------------------------------------------------------------
__global__ void __launch_bounds__(256)
a2bf_concat(const float* __restrict__ f, const float* __restrict__ h)
{
    const size_t i = (size_t)blockIdx.x * 256 + threadIdx.x;   // float4 index
    const int m  = (int)(i >> 9);              // 2048/4 = 512 f4 per row
    const int c4 = (int)(i & 511) << 2;
    const float* src = (c4 < HH) ? (f + (size_t)m * HH + c4)
                                 : (h + (size_t)m * HH + (c4 - HH));
    const float4 v = *(const float4*)src;
    __nv_bfloat16 h0 = __float2bfloat16_rn(v.x);
    __nv_bfloat16 h1 = __float2bfloat16_rn(v.y);
    __nv_bfloat16 h2 = __float2bfloat16_rn(v.z);
    __nv_bfloat16 h3 = __float2bfloat16_rn(v.w);
    __nv_bfloat16 l0 = __float2bfloat16_rn(v.x - __bfloat162float(h0));
    __nv_bfloat16 l1 = __float2bfloat16_rn(v.y - __bfloat162float(h1));
    __nv_bfloat16 l2 = __float2bfloat16_rn(v.z - __bfloat162float(h2));
    __nv_bfloat16 l3 = __float2bfloat16_rn(v.w - __bfloat162float(h3));
    const size_t o = (size_t)m * (2 * HH) + c4;
    *(uint2*)(g_Ahi + o) = make_uint2(pk_bf(h0, h1), pk_bf(h2, h3));
    *(uint2*)(g_Alo + o) = make_uint2(pk_bf(l0, l1), pk_bf(l2, l3));
}

// ---------------------------------------------------------------------------
// W transpose + bf16 hi/lo split:  T[n][k] = split(W[k][n])
// ---------------------------------------------------------------------------
__global__ void __launch_bounds__(256)
wtrans(const float* __restrict__ W, int K, int N,
       __nv_bfloat16* __restrict__ Thi, __nv_bfloat16* __restrict__ Tlo)
{
    __shared__ float t[32][33];
    const int n0 = blockIdx.x * 32, k0 = blockIdx.y * 32;
    const int tx = threadIdx.x & 31, ty = threadIdx.x >> 5;
    #pragma unroll
    for (int i = ty; i < 32; i += 8)
        t[i][tx] = W[(size_t)(k0 + i) * N + n0 + tx];
    __syncthreads();
    #pragma unroll
    for (int i = ty; i < 32; i += 8) {
        float x = t[tx][i];
        __nv_bfloat16 h = __float2bfloat16_rn(x);
        __nv_bfloat16 l = __float2bfloat16_rn(x - __bfloat162float(h));
        size_t o = (size_t)(n0 + i) * K + k0 + tx;
        Thi[o] = h;
        Tlo[o] = l;
    }
}

// ---------------------------------------------------------------------------
// HMMA GEMM + bias + gelu.  C[m][n] = gelu( A[m][:] . Wt[n][:] + bias[n] )
// A bf16 hi/lo [M][K] (pre-converted), Wt bf16 hi/lo [N][K].
// CTA 256(M) x 128(N), 512 threads (16 warps: 8M x 2N, warp tile 32x64).
// K-chunks of 64, 2-stage cp.async double buffer.
// 3-term split: Ahi*Bhi + Alo*Bhi + Ahi*Blo, fp32 accum.
// ---------------------------------------------------------------------------
// Stage layout (row stride 72 bf16 = 144 B):
//   AHI 256x144 = 36864 | ALO 36864 | BHI 128x144 = 18432 | BLO 18432
#define ST_ALO 36864
#define ST_BHI 73728
#define ST_BLO 92160
#define STAGE  110592
#define SMEM_TOTAL (1024 + 2 * STAGE)

__global__ void __launch_bounds__(512, 1)
gemm_bf(const __nv_bfloat16* __restrict__ Ahi, const __nv_bfloat16* __restrict__ Alo,
        int K, int kchunks,
        const __nv_bfloat16* __restrict__ Whi, const __nv_bfloat16* __restrict__ Wlo,
        const float* __restrict__ bias, float* __restrict__ C)
{
    extern __shared__ char smem_raw[];
    float* sBias = (float*)(smem_raw);
    char* sm = smem_raw + 1024;
    const uint32_t smU = smem_u32(sm);

    const int tid = threadIdx.x, wid = tid >> 5, lane = tid & 31;
    const int mBase = blockIdx.y * 256;
    const int nBase = blockIdx.x * 128;
    const int g = lane >> 2, t = lane & 3;
    const int warpM = wid >> 1, warpN = wid & 1;   // 8 (M) x 2 (N)

    // cp.async maps
    const int aRow = tid >> 1, aHalf = (tid & 1);        // A: 2 thr/row, 4 u4 each
    const int bRow = tid >> 2, bQ = (tid & 3);           // B: 4 thr/row, 2 u4 each

    if (tid < 128) sBias[tid] = bias[nBase + tid];

    auto issue = [&](int s, int stage) {
        const uint32_t sb = smU + stage * STAGE;
        const int k0 = s * 64;
        const __nv_bfloat16* ah = Ahi + (size_t)(mBase + aRow) * K + k0 + aHalf * 32;
        const __nv_bfloat16* al = Alo + (size_t)(mBase + aRow) * K + k0 + aHalf * 32;
        const uint32_t ao = sb + aRow * 144 + aHalf * 64;
        #pragma unroll
        for (int j = 0; j < 4; j++) {
            cp_async16(ao + j * 16,          ah + j * 8);
            cp_async16(ao + ST_ALO + j * 16, al + j * 8);
        }
        const __nv_bfloat16* bh = Whi + (size_t)(nBase + bRow) * K + k0 + bQ * 16;
        const __nv_bfloat16* bl = Wlo + (size_t)(nBase + bRow) * K + k0 + bQ * 16;
        const uint32_t bo = sb + bRow * 144 + bQ * 32;
        #pragma unroll
        for (int j = 0; j < 2; j++) {
            cp_async16(bo + ST_BHI + j * 16, bh + j * 8);
            cp_async16(bo + ST_BLO + j * 16, bl + j * 8);
        }
        cp_commit();
    };

    float acc[2][8][4];
    #pragma unroll
    for (int mb = 0; mb < 2; mb++)
        #pragma unroll
        for (int nb = 0; nb < 8; nb++)
            #pragma unroll
            for (int q = 0; q < 4; q++)
                acc[mb][nb][q] = 0.0f;

    issue(0, 0);
    issue(1, 1);

    for (int s = 0; s < kchunks; s++) {
        const int st = s & 1;
        if (s + 1 < kchunks) cp_wait1(); else cp_wait0();
        __syncthreads();

        const __nv_bfloat16* sAhi = (const __nv_bfloat16*)(sm + st * STAGE);
        const __nv_bfloat16* sAlo = (const __nv_bfloat16*)(sm + st * STAGE + ST_ALO);
        const __nv_bfloat16* sBhi = (const __nv_bfloat16*)(sm + st * STAGE + ST_BHI);
        const __nv_bfloat16* sBlo = (const __nv_bfloat16*)(sm + st * STAGE + ST_BLO);

        #pragma unroll
        for (int kk = 0; kk < 4; kk++) {
            const int kb = kk * 16;
            uint32_t ah[2][4], al[2][4];
            #pragma unroll
            for (int mb = 0; mb < 2; mb++) {
                const int r0 = warpM * 32 + mb * 16 + g;
                const __nv_bfloat16* ph = sAhi + r0 * 72 + kb + t * 2;
                ah[mb][0] = *(const uint32_t*)(ph);
                ah[mb][1] = *(const uint32_t*)(ph + 8 * 72);
                ah[mb][2] = *(const uint32_t*)(ph + 8);
                ah[mb][3] = *(const uint32_t*)(ph + 8 * 72 + 8);
                const __nv_bfloat16* pl = sAlo + r0 * 72 + kb + t * 2;
                al[mb][0] = *(const uint32_t*)(pl);
                al[mb][1] = *(const uint32_t*)(pl + 8 * 72);
                al[mb][2] = *(const uint32_t*)(pl + 8);
                al[mb][3] = *(const uint32_t*)(pl + 8 * 72 + 8);
            }
            #pragma unroll
            for (int nb = 0; nb < 8; nb++) {
                const int n0 = warpN * 64 + nb * 8 + g;
                const __nv_bfloat16* pbh = sBhi + n0 * 72 + kb + t * 2;
                const __nv_bfloat16* pbl = sBlo + n0 * 72 + kb + t * 2;
                const uint32_t bh0 = *(const uint32_t*)(pbh);
                const uint32_t bh1 = *(const uint32_t*)(pbh + 8);
                const uint32_t bl0 = *(const uint32_t*)(pbl);
                const uint32_t bl1 = *(const uint32_t*)(pbl + 8);
                #pragma unroll
                for (int mb = 0; mb < 2; mb++) {
                    mma_bf16_16816(acc[mb][nb], ah[mb], bh0, bh1);
                    mma_bf16_16816(acc[mb][nb], al[mb], bh0, bh1);
                    mma_bf16_16816(acc[mb][nb], ah[mb], bl0, bl1);
                }
            }
        }
        __syncthreads();
        if (s + 2 < kchunks) issue(s + 2, st);
    }

    // ---- epilogue: bias + gelu
    #pragma unroll
    for (int mb = 0; mb < 2; mb++) {
        #pragma unroll
        for (int nb = 0; nb < 8; nb++) {
            const int row0 = mBase + warpM * 32 + mb * 16 + g;
            const int colL = warpN * 64 + nb * 8 + t * 2;
            const int col  = nBase + colL;
            float2 o0, o1;
            o0.x = gelu_exact(acc[mb][nb][0] + sBias[colL + 0]);
            o0.y = gelu_exact(acc[mb][nb][1] + sBias[colL + 1]);
            o1.x = gelu_exact(acc[mb][nb][2] + sBias[colL + 0]);
            o1.y = gelu_exact(acc[mb][nb][3] + sBias[colL + 1]);
            *(float2*)(C + (size_t)row0 * HH + col)       = o0;
            *(float2*)(C + (size_t)(row0 + 8) * HH + col) = o1;
        }
    }
}

// ---------------------------------------------------------------------------
// Bucket build: deterministic per-(b,t) index lists, ordered by ascending l.
// ---------------------------------------------------------------------------
__global__ void __launch_bounds__(256)
bucket_build(const int* __restrict__ ids)
{
    __shared__ int s_ids[LL];
    __shared__ int s_ofs[TT + 1];
    const int b = blockIdx.x, tid = threadIdx.x;

    for (int i = tid; i < LL; i += 256) s_ids[i] = ids[b * LL + i];
    for (int i = tid; i <= TT; i += 256) s_ofs[i] = 0;
    __syncthreads();
    for (int i = tid; i < LL; i += 256) atomicAdd(&s_ofs[s_ids[i] + 1], 1);
    __syncthreads();
    if (tid == 0) {
        int run = 0;
        #pragma unroll 4
        for (int i = 1; i <= TT; i++) { run += s_ofs[i]; s_ofs[i] = run; }
    }
    __syncthreads();
    for (int i = tid; i <= TT; i += 256) g_offsets[b * (TT + 1) + i] = s_ofs[i];

    int ofs = s_ofs[tid];
    for (int l = 0; l < LL; l++)
        if (s_ids[l] == tid) g_entries[b * LL + ofs++] = l;
}

// ---------------------------------------------------------------------------
// Segment-sum apply: sum own rows, emit bf16 hi/lo split directly (GEMM2 A).
// ---------------------------------------------------------------------------
__global__ void __launch_bounds__(256)
segsum_apply()
{
    const int t = blockIdx.x, b = blockIdx.y, tid = threadIdx.x;
    const int start = g_offsets[b * (TT + 1) + t];
    const int end   = g_offsets[b * (TT + 1) + t + 1];
    const float4* base = reinterpret_cast<const float4*>(g_seq) + (size_t)b * LL * (HH / 4) + tid;

    float4 acc = make_float4(0.f, 0.f, 0.f, 0.f);
    for (int i = start; i < end; i++) {
        const int l = __ldg(&g_entries[b * LL + i]);
        const float4 v = base[(size_t)l * (HH / 4)];
        acc.x += v.x; acc.y += v.y; acc.z += v.z; acc.w += v.w;
    }
    __nv_bfloat16 h0 = __float2bfloat16_rn(acc.x);
    __nv_bfloat16 h1 = __float2bfloat16_rn(acc.y);
    __nv_bfloat16 h2 = __float2bfloat16_rn(acc.z);
    __nv_bfloat16 h3 = __float2bfloat16_rn(acc.w);
    __nv_bfloat16 l0 = __float2bfloat16_rn(acc.x - __bfloat162float(h0));
    __nv_bfloat16 l1 = __float2bfloat16_rn(acc.y - __bfloat162float(h1));
    __nv_bfloat16 l2 = __float2bfloat16_rn(acc.z - __bfloat162float(h2));
    __nv_bfloat16 l3 = __float2bfloat16_rn(acc.w - __bfloat162float(h3));
    const size_t o = ((size_t)(b * TT + t)) * HH + tid * 4;
    *(uint2*)(g_c1hi + o) = make_uint2(pk_bf(h0, h1), pk_bf(h2, h3));
    *(uint2*)(g_c1lo + o) = make_uint2(pk_bf(l0, l1), pk_bf(l2, l3));
}

// ---------------------------------------------------------------------------
// Gather: out[b,l,:] = cell2[b, ids[b,l], :]
// ---------------------------------------------------------------------------
__global__ void __launch_bounds__(256)
gather_kernel(const int* __restrict__ ids, float* __restrict__ out)
{
    const int l = blockIdx.x, b = blockIdx.y, tid = threadIdx.x;
    const int t = ids[b * LL + l];
    const float4 v = reinterpret_cast<const float4*>(g_cell2)[((size_t)(b * TT + t)) * (HH / 4) + tid];
    reinterpret_cast<float4*>(out)[((size_t)(b * LL + l)) * (HH / 4) + tid] = v;
}

// ---------------------------------------------------------------------------
extern "C" void kernel_launch(void* const* d_in, const int* in_sizes, int n_in,
                              void* d_out, int out_size)
{
    const float* former = (const float*)d_in[0];
    const float* hidden = (const float*)d_in[1];
    const int*   ids    = (const int*)  d_in[2];
    const float* Wd     = (const float*)d_in[4];   // [2048, 1024]
    const float* bd     = (const float*)d_in[5];
    const float* Wr     = (const float*)d_in[6];   // [1024, 1024]
    const float* br     = (const float*)d_in[7];
    float* out = (float*)d_out;

    float *seq, *c2;
    __nv_bfloat16 *ahi, *alo, *c1h, *c1l, *wdh, *wdl, *wrh, *wrl;
    cudaGetSymbolAddress((void**)&seq, g_seq);
    cudaGetSymbolAddress((void**)&c2,  g_cell2);
    cudaGetSymbolAddress((void**)&ahi, g_Ahi);
    cudaGetSymbolAddress((void**)&alo, g_Alo);
    cudaGetSymbolAddress((void**)&c1h, g_c1hi);
    cudaGetSymbolAddress((void**)&c1l, g_c1lo);
    cudaGetSymbolAddress((void**)&wdh, g_WdT_hi);
    cudaGetSymbolAddress((void**)&wdl, g_WdT_lo);
    cudaGetSymbolAddress((void**)&wrh, g_WrT_hi);
    cudaGetSymbolAddress((void**)&wrl, g_WrT_lo);

    cudaFuncSetAttribute(gemm_bf, cudaFuncAttributeMaxDynamicSharedMemorySize, SMEM_TOTAL);

    // Prep passes (independent): W transpose+split, A convert, bucket lists
    wtrans<<<dim3(32, 64), 256>>>(Wd, 2 * HH, HH, wdh, wdl);
    wtrans<<<dim3(32, 32), 256>>>(Wr, HH, HH, wrh, wrl);
    a2bf_concat<<<(M1 * 2 * HH / 4) / 256, 256>>>(former, hidden);
    bucket_build<<<BB, 256>>>(ids);

    // Stage 1: seq = gelu(concat @ W_down + b_down)
    gemm_bf<<<dim3(HH / 128, M1 / 256), 512, SMEM_TOTAL>>>(
        ahi, alo, 2 * HH, 32, wdh, wdl, bd, seq);

    // Stage 2: segment sum -> cell1 (bf16 hi/lo)
    segsum_apply<<<dim3(TT, BB), 256>>>();

    // Stage 3: cell2 = gelu(cell1 @ W_row + b_row)
    gemm_bf<<<dim3(HH / 128, M2 / 256), 512, SMEM_TOTAL>>>(
        c1h, c1l, HH, 16, wrh, wrl, br, c2);

    // Stage 4: gather
    gather_kernel<<<dim3(LL, BB), 256>>>(ids, out);
}

// round 15
// speedup vs baseline: 1.1661x; 1.1661x over previous
#include <cuda_runtime.h>
#include <cuda_bf16.h>
#include <math.h>
#include <stdint.h>

#define BB   8
#define LL   2048
#define HH   1024
#define TT   256
#define M1   (BB * LL)    // 16384
#define M2   (BB * TT)    // 2048

// ---------------- scratch (__device__ globals; no allocation allowed) -------
__device__ float g_seq[(size_t)M1 * HH];                                // 64 MiB
__device__ float g_cell2[(size_t)M2 * HH];                              //  8 MiB
__device__ __align__(16) __nv_bfloat16 g_Ahi[(size_t)M1 * 2 * HH];      // 64 MiB
__device__ __align__(16) __nv_bfloat16 g_Alo[(size_t)M1 * 2 * HH];      // 64 MiB
__device__ __align__(16) __nv_bfloat16 g_c1hi[(size_t)M2 * HH];         //  4 MiB
__device__ __align__(16) __nv_bfloat16 g_c1lo[(size_t)M2 * HH];         //  4 MiB
__device__ __align__(16) __nv_bfloat16 g_WdT_hi[(size_t)HH * 2 * HH];   //  4 MiB
__device__ __align__(16) __nv_bfloat16 g_WdT_lo[(size_t)HH * 2 * HH];
__device__ __align__(16) __nv_bfloat16 g_WrT_hi[(size_t)HH * HH];       //  2 MiB
__device__ __align__(16) __nv_bfloat16 g_WrT_lo[(size_t)HH * HH];
__device__ int g_entries[BB * LL];
__device__ int g_offsets[BB * (TT + 1)];

// ---------------- helpers ----------------------------------------------------
__device__ __forceinline__ uint32_t smem_u32(const void* p) {
    uint32_t a;
    asm("{ .reg .u64 t; cvta.to.shared.u64 t, %1; cvt.u32.u64 %0, t; }" : "=r"(a) : "l"(p));
    return a;
}
__device__ __forceinline__ uint32_t pk_bf(__nv_bfloat16 a, __nv_bfloat16 b) {
    return (uint32_t)__bfloat16_as_ushort(a) | ((uint32_t)__bfloat16_as_ushort(b) << 16);
}
__device__ __forceinline__ float gelu_exact(float x) {
    return 0.5f * x * (1.0f + erff(x * 0.7071067811865475244f));
}
__device__ __forceinline__ void cp_async16(uint32_t dst, const void* src) {
    asm volatile("cp.async.cg.shared.global [%0], [%1], 16;" :: "r"(dst), "l"(src) : "memory");
}
__device__ __forceinline__ void cp_commit() { asm volatile("cp.async.commit_group;" ::: "memory"); }
__device__ __forceinline__ void cp_wait1()  { asm volatile("cp.async.wait_group 1;" ::: "memory"); }
__device__ __forceinline__ void cp_wait0()  { asm volatile("cp.async.wait_group 0;" ::: "memory"); }
__device__ __forceinline__ void mma_bf16_16816(float* c, const uint32_t* a,
                                               uint32_t b0, uint32_t b1) {
    asm volatile(
        "mma.sync.aligned.m16n8k16.row.col.f32.bf16.bf16.f32 "
        "{%0,%1,%2,%3}, {%4,%5,%6,%7}, {%8,%9}, {%0,%1,%2,%3};"
        : "+f"(c[0]), "+f"(c[1]), "+f"(c[2]), "+f"(c[3])
        : "r"(a[0]), "r"(a[1]), "r"(a[2]), "r"(a[3]), "r"(b0), "r"(b1));
}

// ---------------------------------------------------------------------------
// A pre-convert: g_Ahi/g_Alo[m][k] = bf16 hi/lo split of concat(former,hidden)
// ---------------------------------------------------------------------------
__global__ void __launch_bounds__(256)
a2bf_concat(const float* __restrict__ f, const float* __restrict__ h)
{
    const size_t i = (size_t)blockIdx.x * 256 + threadIdx.x;   // float4 index
    const int m  = (int)(i >> 9);              // 2048/4 = 512 f4 per row
    const int c4 = (int)(i & 511) << 2;
    const float* src = (c4 < HH) ? (f + (size_t)m * HH + c4)
                                 : (h + (size_t)m * HH + (c4 - HH));
    const float4 v = *(const float4*)src;
    __nv_bfloat16 h0 = __float2bfloat16_rn(v.x);
    __nv_bfloat16 h1 = __float2bfloat16_rn(v.y);
    __nv_bfloat16 h2 = __float2bfloat16_rn(v.z);
    __nv_bfloat16 h3 = __float2bfloat16_rn(v.w);
    __nv_bfloat16 l0 = __float2bfloat16_rn(v.x - __bfloat162float(h0));
    __nv_bfloat16 l1 = __float2bfloat16_rn(v.y - __bfloat162float(h1));
    __nv_bfloat16 l2 = __float2bfloat16_rn(v.z - __bfloat162float(h2));
    __nv_bfloat16 l3 = __float2bfloat16_rn(v.w - __bfloat162float(h3));
    const size_t o = (size_t)m * (2 * HH) + c4;
    *(uint2*)(g_Ahi + o) = make_uint2(pk_bf(h0, h1), pk_bf(h2, h3));
    *(uint2*)(g_Alo + o) = make_uint2(pk_bf(l0, l1), pk_bf(l2, l3));
}

// ---------------------------------------------------------------------------
// W transpose + bf16 hi/lo split:  T[n][k] = split(W[k][n])
// ---------------------------------------------------------------------------
__global__ void __launch_bounds__(256)
wtrans(const float* __restrict__ W, int K, int N,
       __nv_bfloat16* __restrict__ Thi, __nv_bfloat16* __restrict__ Tlo)
{
    __shared__ float t[32][33];
    const int n0 = blockIdx.x * 32, k0 = blockIdx.y * 32;
    const int tx = threadIdx.x & 31, ty = threadIdx.x >> 5;
    #pragma unroll
    for (int i = ty; i < 32; i += 8)
        t[i][tx] = W[(size_t)(k0 + i) * N + n0 + tx];
    __syncthreads();
    #pragma unroll
    for (int i = ty; i < 32; i += 8) {
        float x = t[tx][i];
        __nv_bfloat16 h = __float2bfloat16_rn(x);
        __nv_bfloat16 l = __float2bfloat16_rn(x - __bfloat162float(h));
        size_t o = (size_t)(n0 + i) * K + k0 + tx;
        Thi[o] = h;
        Tlo[o] = l;
    }
}

// ---------------------------------------------------------------------------
// HMMA GEMM + bias + gelu.  C[m][n] = gelu( A[m][:] . Wt[n][:] + bias[n] )
// A bf16 hi/lo [M][K] (pre-converted), Wt bf16 hi/lo [N][K].
// CTA 128(M) x 128(N), 512 threads (16 warps: 4M x 4N, warp tile 32x32).
// 32 accumulators/thread -> fits the 128-reg budget at 512 thr (no spills).
// K-chunks of 64, 2-stage cp.async double buffer.
// 3-term split: Ahi*Bhi + Alo*Bhi + Ahi*Blo, fp32 accum.
// ---------------------------------------------------------------------------
// Stage layout (row stride 72 bf16 = 144 B), 128 rows each:
//   AHI 18432 | ALO 18432 | BHI 18432 | BLO 18432
#define ST_ALO 18432
#define ST_BHI 36864
#define ST_BLO 55296
#define STAGE  73728
#define SMEM_TOTAL (1024 + 2 * STAGE)

__global__ void __launch_bounds__(512, 1)
gemm_bf(const __nv_bfloat16* __restrict__ Ahi, const __nv_bfloat16* __restrict__ Alo,
        int K, int kchunks,
        const __nv_bfloat16* __restrict__ Whi, const __nv_bfloat16* __restrict__ Wlo,
        const float* __restrict__ bias, float* __restrict__ C)
{
    extern __shared__ char smem_raw[];
    float* sBias = (float*)(smem_raw);
    char* sm = smem_raw + 1024;
    const uint32_t smU = smem_u32(sm);

    const int tid = threadIdx.x, wid = tid >> 5, lane = tid & 31;
    const int mBase = blockIdx.y * 128;
    const int nBase = blockIdx.x * 128;
    const int g = lane >> 2, t = lane & 3;
    const int warpM = wid >> 2, warpN = wid & 3;   // 4 (M) x 4 (N)

    // cp.async map: 4 threads/row, each covers 32 B (2 x 16B)
    const int ldRow = tid >> 2, ldQ = tid & 3;

    if (tid < 128) sBias[tid] = bias[nBase + tid];

    auto issue = [&](int s, int stage) {
        const uint32_t sb = smU + stage * STAGE;
        const int k0 = s * 64;
        const uint32_t o = ldRow * 144 + ldQ * 32;
        const __nv_bfloat16* ah = Ahi + (size_t)(mBase + ldRow) * K + k0 + ldQ * 16;
        const __nv_bfloat16* al = Alo + (size_t)(mBase + ldRow) * K + k0 + ldQ * 16;
        const __nv_bfloat16* bh = Whi + (size_t)(nBase + ldRow) * K + k0 + ldQ * 16;
        const __nv_bfloat16* bl = Wlo + (size_t)(nBase + ldRow) * K + k0 + ldQ * 16;
        #pragma unroll
        for (int j = 0; j < 2; j++) {
            cp_async16(sb + o + j * 16,          ah + j * 8);
            cp_async16(sb + ST_ALO + o + j * 16, al + j * 8);
            cp_async16(sb + ST_BHI + o + j * 16, bh + j * 8);
            cp_async16(sb + ST_BLO + o + j * 16, bl + j * 8);
        }
        cp_commit();
    };

    float acc[2][4][4];
    #pragma unroll
    for (int mb = 0; mb < 2; mb++)
        #pragma unroll
        for (int nb = 0; nb < 4; nb++)
            #pragma unroll
            for (int q = 0; q < 4; q++)
                acc[mb][nb][q] = 0.0f;

    issue(0, 0);
    issue(1, 1);

    for (int s = 0; s < kchunks; s++) {
        const int st = s & 1;
        if (s + 1 < kchunks) cp_wait1(); else cp_wait0();
        __syncthreads();

        const __nv_bfloat16* sAhi = (const __nv_bfloat16*)(sm + st * STAGE);
        const __nv_bfloat16* sAlo = (const __nv_bfloat16*)(sm + st * STAGE + ST_ALO);
        const __nv_bfloat16* sBhi = (const __nv_bfloat16*)(sm + st * STAGE + ST_BHI);
        const __nv_bfloat16* sBlo = (const __nv_bfloat16*)(sm + st * STAGE + ST_BLO);

        #pragma unroll
        for (int kk = 0; kk < 4; kk++) {
            const int kb = kk * 16;
            uint32_t ah[2][4], al[2][4];
            #pragma unroll
            for (int mb = 0; mb < 2; mb++) {
                const int r0 = warpM * 32 + mb * 16 + g;
                const __nv_bfloat16* ph = sAhi + r0 * 72 + kb + t * 2;
                ah[mb][0] = *(const uint32_t*)(ph);
                ah[mb][1] = *(const uint32_t*)(ph + 8 * 72);
                ah[mb][2] = *(const uint32_t*)(ph + 8);
                ah[mb][3] = *(const uint32_t*)(ph + 8 * 72 + 8);
                const __nv_bfloat16* pl = sAlo + r0 * 72 + kb + t * 2;
                al[mb][0] = *(const uint32_t*)(pl);
                al[mb][1] = *(const uint32_t*)(pl + 8 * 72);
                al[mb][2] = *(const uint32_t*)(pl + 8);
                al[mb][3] = *(const uint32_t*)(pl + 8 * 72 + 8);
            }
            #pragma unroll
            for (int nb = 0; nb < 4; nb++) {
                const int n0 = warpN * 32 + nb * 8 + g;
                const __nv_bfloat16* pbh = sBhi + n0 * 72 + kb + t * 2;
                const __nv_bfloat16* pbl = sBlo + n0 * 72 + kb + t * 2;
                const uint32_t bh0 = *(const uint32_t*)(pbh);
                const uint32_t bh1 = *(const uint32_t*)(pbh + 8);
                const uint32_t bl0 = *(const uint32_t*)(pbl);
                const uint32_t bl1 = *(const uint32_t*)(pbl + 8);
                #pragma unroll
                for (int mb = 0; mb < 2; mb++) {
                    mma_bf16_16816(acc[mb][nb], ah[mb], bh0, bh1);
                    mma_bf16_16816(acc[mb][nb], al[mb], bh0, bh1);
                    mma_bf16_16816(acc[mb][nb], ah[mb], bl0, bl1);
                }
            }
        }
        __syncthreads();
        if (s + 2 < kchunks) issue(s + 2, st);
    }

    // ---- epilogue: bias + gelu
    #pragma unroll
    for (int mb = 0; mb < 2; mb++) {
        #pragma unroll
        for (int nb = 0; nb < 4; nb++) {
            const int row0 = mBase + warpM * 32 + mb * 16 + g;
            const int colL = warpN * 32 + nb * 8 + t * 2;
            const int col  = nBase + colL;
            float2 o0, o1;
            o0.x = gelu_exact(acc[mb][nb][0] + sBias[colL + 0]);
            o0.y = gelu_exact(acc[mb][nb][1] + sBias[colL + 1]);
            o1.x = gelu_exact(acc[mb][nb][2] + sBias[colL + 0]);
            o1.y = gelu_exact(acc[mb][nb][3] + sBias[colL + 1]);
            *(float2*)(C + (size_t)row0 * HH + col)       = o0;
            *(float2*)(C + (size_t)(row0 + 8) * HH + col) = o1;
        }
    }
}

// ---------------------------------------------------------------------------
// Bucket build: deterministic per-(b,t) index lists, ordered by ascending l.
// ---------------------------------------------------------------------------
__global__ void __launch_bounds__(256)
bucket_build(const int* __restrict__ ids)
{
    __shared__ int s_ids[LL];
    __shared__ int s_ofs[TT + 1];
    const int b = blockIdx.x, tid = threadIdx.x;

    for (int i = tid; i < LL; i += 256) s_ids[i] = ids[b * LL + i];
    for (int i = tid; i <= TT; i += 256) s_ofs[i] = 0;
    __syncthreads();
    for (int i = tid; i < LL; i += 256) atomicAdd(&s_ofs[s_ids[i] + 1], 1);
    __syncthreads();
    if (tid == 0) {
        int run = 0;
        #pragma unroll 4
        for (int i = 1; i <= TT; i++) { run += s_ofs[i]; s_ofs[i] = run; }
    }
    __syncthreads();
    for (int i = tid; i <= TT; i += 256) g_offsets[b * (TT + 1) + i] = s_ofs[i];

    int ofs = s_ofs[tid];
    #pragma unroll 8
    for (int l = 0; l < LL; l++)
        if (s_ids[l] == tid) g_entries[b * LL + ofs++] = l;
}

// ---------------------------------------------------------------------------
// Segment-sum apply: sum own rows, emit bf16 hi/lo split directly (GEMM2 A).
// ---------------------------------------------------------------------------
__global__ void __launch_bounds__(256)
segsum_apply()
{
    const int t = blockIdx.x, b = blockIdx.y, tid = threadIdx.x;
    const int start = g_offsets[b * (TT + 1) + t];
    const int end   = g_offsets[b * (TT + 1) + t + 1];
    const float4* base = reinterpret_cast<const float4*>(g_seq) + (size_t)b * LL * (HH / 4) + tid;

    float4 acc = make_float4(0.f, 0.f, 0.f, 0.f);
    for (int i = start; i < end; i++) {
        const int l = __ldg(&g_entries[b * LL + i]);
        const float4 v = base[(size_t)l * (HH / 4)];
        acc.x += v.x; acc.y += v.y; acc.z += v.z; acc.w += v.w;
    }
    __nv_bfloat16 h0 = __float2bfloat16_rn(acc.x);
    __nv_bfloat16 h1 = __float2bfloat16_rn(acc.y);
    __nv_bfloat16 h2 = __float2bfloat16_rn(acc.z);
    __nv_bfloat16 h3 = __float2bfloat16_rn(acc.w);
    __nv_bfloat16 l0 = __float2bfloat16_rn(acc.x - __bfloat162float(h0));
    __nv_bfloat16 l1 = __float2bfloat16_rn(acc.y - __bfloat162float(h1));
    __nv_bfloat16 l2 = __float2bfloat16_rn(acc.z - __bfloat162float(h2));
    __nv_bfloat16 l3 = __float2bfloat16_rn(acc.w - __bfloat162float(h3));
    const size_t o = ((size_t)(b * TT + t)) * HH + tid * 4;
    *(uint2*)(g_c1hi + o) = make_uint2(pk_bf(h0, h1), pk_bf(h2, h3));
    *(uint2*)(g_c1lo + o) = make_uint2(pk_bf(l0, l1), pk_bf(l2, l3));
}

// ---------------------------------------------------------------------------
// Gather: out[b,l,:] = cell2[b, ids[b,l], :]
// ---------------------------------------------------------------------------
__global__ void __launch_bounds__(256)
gather_kernel(const int* __restrict__ ids, float* __restrict__ out)
{
    const int l = blockIdx.x, b = blockIdx.y, tid = threadIdx.x;
    const int t = ids[b * LL + l];
    const float4 v = reinterpret_cast<const float4*>(g_cell2)[((size_t)(b * TT + t)) * (HH / 4) + tid];
    reinterpret_cast<float4*>(out)[((size_t)(b * LL + l)) * (HH / 4) + tid] = v;
}

// ---------------------------------------------------------------------------
extern "C" void kernel_launch(void* const* d_in, const int* in_sizes, int n_in,
                              void* d_out, int out_size)
{
    const float* former = (const float*)d_in[0];
    const float* hidden = (const float*)d_in[1];
    const int*   ids    = (const int*)  d_in[2];
    const float* Wd     = (const float*)d_in[4];   // [2048, 1024]
    const float* bd     = (const float*)d_in[5];
    const float* Wr     = (const float*)d_in[6];   // [1024, 1024]
    const float* br     = (const float*)d_in[7];
    float* out = (float*)d_out;

    float *seq, *c2;
    __nv_bfloat16 *ahi, *alo, *c1h, *c1l, *wdh, *wdl, *wrh, *wrl;
    cudaGetSymbolAddress((void**)&seq, g_seq);
    cudaGetSymbolAddress((void**)&c2,  g_cell2);
    cudaGetSymbolAddress((void**)&ahi, g_Ahi);
    cudaGetSymbolAddress((void**)&alo, g_Alo);
    cudaGetSymbolAddress((void**)&c1h, g_c1hi);
    cudaGetSymbolAddress((void**)&c1l, g_c1lo);
    cudaGetSymbolAddress((void**)&wdh, g_WdT_hi);
    cudaGetSymbolAddress((void**)&wdl, g_WdT_lo);
    cudaGetSymbolAddress((void**)&wrh, g_WrT_hi);
    cudaGetSymbolAddress((void**)&wrl, g_WrT_lo);

    cudaFuncSetAttribute(gemm_bf, cudaFuncAttributeMaxDynamicSharedMemorySize, SMEM_TOTAL);

    // Prep passes (independent): W transpose+split, A convert, bucket lists
    wtrans<<<dim3(32, 64), 256>>>(Wd, 2 * HH, HH, wdh, wdl);
    wtrans<<<dim3(32, 32), 256>>>(Wr, HH, HH, wrh, wrl);
    a2bf_concat<<<(M1 * 2 * HH / 4) / 256, 256>>>(former, hidden);
    bucket_build<<<BB, 256>>>(ids);

    // Stage 1: seq = gelu(concat @ W_down + b_down)
    gemm_bf<<<dim3(HH / 128, M1 / 128), 512, SMEM_TOTAL>>>(
        ahi, alo, 2 * HH, 32, wdh, wdl, bd, seq);

    // Stage 2: segment sum -> cell1 (bf16 hi/lo)
    segsum_apply<<<dim3(TT, BB), 256>>>();

    // Stage 3: cell2 = gelu(cell1 @ W_row + b_row)
    gemm_bf<<<dim3(HH / 128, M2 / 128), 512, SMEM_TOTAL>>>(
        c1h, c1l, HH, 16, wrh, wrl, br, c2);

    // Stage 4: gather
    gather_kernel<<<dim3(LL, BB), 256>>>(ids, out);
}